// round 12
// baseline (speedup 1.0000x reference)
#include <cuda_runtime.h>
#include <math.h>
#include <stdint.h>

#define N_NODES 200000
#define E_EDGES 800000
#define NBATCH  16
#define PK      208   // 193 padded to multiple of 16

// ---------------- scratch (static; no cudaMalloc) ----------------
__device__ __align__(16) float    g_x   [(size_t)N_NODES * 128];
__device__ __align__(16) float    g_xp  [(size_t)N_NODES * 128];
__device__ __align__(16) float    g_aggA[(size_t)N_NODES * 64];
__device__ __align__(16) float    g_aggB[(size_t)N_NODES * 64];
__device__ __align__(16) float    g_y   [(size_t)N_NODES * 64];
__device__ __align__(16) float    g_rn  [N_NODES];
__device__ __align__(16) float    g_deg [N_NODES];
__device__ __align__(16) unsigned g_gmax[NBATCH * 64];
__device__ __align__(16) float    g_gsum[NBATCH * 64];
__device__ __align__(16) float    g_cnt [NBATCH];

// ---------------- helpers ----------------
__device__ __forceinline__ unsigned fenc(float f) {
    unsigned u = __float_as_uint(f);
    return (u & 0x80000000u) ? ~u : (u | 0x80000000u);
}
__device__ __forceinline__ float fdec(unsigned u) {
    return (u & 0x80000000u) ? __uint_as_float(u & 0x7FFFFFFFu) : __uint_as_float(~u);
}

__global__ void zero_f(float* p, size_t n) {
    size_t i = (size_t)blockIdx.x * blockDim.x + threadIdx.x;
    if (i < n) p[i] = 0.f;
}

__global__ void pool_init_kernel() {
    int i = blockIdx.x * blockDim.x + threadIdx.x;
    if (i < NBATCH * 64) { g_gmax[i] = 0u; g_gsum[i] = 0.f; }
    if (i < NBATCH) g_cnt[i] = 0.f;
}

__global__ void deg_kernel(const int* __restrict__ dst) {
    int e = blockIdx.x * blockDim.x + threadIdx.x;
    if (e < E_EDGES) atomicAdd(&g_deg[dst[e]], 1.f);
}
__global__ void deginv_kernel() {
    int n = blockIdx.x * blockDim.x + threadIdx.x;
    if (n < N_NODES) g_deg[n] = 1.f / fmaxf(g_deg[n], 1.f);
}

// ---------------- tf32 split helpers ----------------
__device__ __forceinline__ void split_tf32(float x, uint32_t& h, uint32_t& l) {
    uint32_t hb;
    asm("cvt.rna.tf32.f32 %0, %1;" : "=r"(hb) : "f"(x));
    h = hb;
    l = __float_as_uint(x - __uint_as_float(hb));
}

__device__ __forceinline__ void mma8(float* c, const uint32_t* a, const uint32_t* b) {
    asm("mma.sync.aligned.m16n8k8.row.col.f32.tf32.tf32.f32 "
        "{%0,%1,%2,%3}, {%4,%5,%6,%7}, {%8,%9}, {%0,%1,%2,%3};"
        : "+f"(c[0]), "+f"(c[1]), "+f"(c[2]), "+f"(c[3])
        : "r"(a[0]), "r"(a[1]), "r"(a[2]), "r"(a[3]), "r"(b[0]), "r"(b[1]));
}

// conflict-free swizzled indices (BM=64 A-tile; 4-byte elements)
__device__ __forceinline__ int idxA(int k, int m) { return k * 64 + (m ^ ((k & 3) << 3)); }
template<int BN>
__device__ __forceinline__ int idxB(int k, int n) { return k * BN + (n ^ ((k & 3) << 3)); }

// one BK=16 tile of split-tf32 mma; block tile 64 x BN, 8 warps as 2M x 4N.
// A and B both pre-split into separate hi/lo uint32 SMEM arrays.
template<int BN, int NI>
__device__ __forceinline__ void mma_ktile(const uint32_t* __restrict__ Ah,
                                          const uint32_t* __restrict__ Al,
                                          const uint32_t* __restrict__ Bh,
                                          const uint32_t* __restrict__ Bl,
                                          int wm, int wn, int gid, int tig,
                                          float (&acc)[2][NI][4]) {
#pragma unroll
    for (int kk = 0; kk < 2; kk++) {
        const int kb = kk * 8 + tig;
        uint32_t aH[2][4], aL[2][4];
#pragma unroll
        for (int mi = 0; mi < 2; mi++) {
            int r = wm + mi * 16 + gid;
            aH[mi][0] = Ah[idxA(kb,     r    )];  aL[mi][0] = Al[idxA(kb,     r    )];
            aH[mi][1] = Ah[idxA(kb,     r + 8)];  aL[mi][1] = Al[idxA(kb,     r + 8)];
            aH[mi][2] = Ah[idxA(kb + 4, r    )];  aL[mi][2] = Al[idxA(kb + 4, r    )];
            aH[mi][3] = Ah[idxA(kb + 4, r + 8)];  aL[mi][3] = Al[idxA(kb + 4, r + 8)];
        }
#pragma unroll
        for (int ni = 0; ni < NI; ni++) {
            int n = wn + ni * 8 + gid;
            uint32_t bh[2], bl[2];
            bh[0] = Bh[idxB<BN>(kb, n)];     bh[1] = Bh[idxB<BN>(kb + 4, n)];
            bl[0] = Bl[idxB<BN>(kb, n)];     bl[1] = Bl[idxB<BN>(kb + 4, n)];
#pragma unroll
            for (int mi = 0; mi < 2; mi++) {
                mma8(acc[mi][ni], aH[mi], bh);
                mma8(acc[mi][ni], aH[mi], bl);
                mma8(acc[mi][ni], aL[mi], bh);
            }
        }
    }
}

// ---------------- fused feature gather ----------------
__device__ __forceinline__ float gatherA(const float* __restrict__ nf, const float* __restrict__ cfgf,
                                         const int* __restrict__ opc,
                                         const float* __restrict__ opE, const float* __restrict__ tyE,
                                         int n, int c) {
    if (c < 139) return nf[(size_t)n * 140 + c];
    if (c < 143) { int ty = (int)nf[(size_t)n * 140 + 139]; return tyE[ty * 4 + (c - 139)]; }
    if (c < 175) return opE[opc[n] * 32 + (c - 143)];
    if (c < 193) return cfgf[(size_t)n * 18 + (c - 175)];
    return 0.f;
}

// ---------------- initial GEMM: x = relu(gather(feat) @ W + b), (N,128) ----
// BM=64, BN=128, 8 warps (2M x 4N), NI=4.  lin_w padding folded into B-load.
__global__ __launch_bounds__(256, 2) void gemm_initial(
    const float* __restrict__ nf, const float* __restrict__ cfgf, const int* __restrict__ opc,
    const float* __restrict__ opE, const float* __restrict__ tyE,
    const float* __restrict__ lin_w,
    const float* __restrict__ bias, float* __restrict__ X)
{
    constexpr int BN = 128, NI = 4;
    __shared__ uint32_t Ah[16 * 64];
    __shared__ uint32_t Al[16 * 64];
    __shared__ uint32_t Bh[16 * BN];
    __shared__ uint32_t Bl[16 * BN];
    const int tid = threadIdx.x, lane = tid & 31, wid = tid >> 5;
    const int gid = lane >> 2, tig = lane & 3;
    const int wm = (wid & 1) * 32, wn = (wid >> 1) * (BN / 4);
    const int m0 = blockIdx.x * 64;
    float acc[2][NI][4] = {};

    for (int k0 = 0; k0 < PK; k0 += 16) {
#pragma unroll
        for (int i = 0; i < 4; i++) {
            int idx = tid + i * 256; int m = idx >> 4, k = idx & 15;
            int mg = m0 + m, kg = k0 + k;
            float v = (mg < N_NODES) ? gatherA(nf, cfgf, opc, opE, tyE, mg, kg) : 0.f;
            uint32_t h, l; split_tf32(v, h, l);
            Ah[idxA(k, m)] = h; Al[idxA(k, m)] = l;
        }
#pragma unroll
        for (int i = 0; i < 8; i++) {
            int idx = tid + i * 256; int k = idx / BN, n = idx % BN;
            int kg = k0 + k;
            float v = (kg < 193) ? lin_w[kg * 128 + n] : 0.f;
            uint32_t h, l; split_tf32(v, h, l);
            Bh[idxB<BN>(k, n)] = h; Bl[idxB<BN>(k, n)] = l;
        }
        __syncthreads();
        mma_ktile<BN, NI>(Ah, Al, Bh, Bl, wm, wn, gid, tig, acc);
        __syncthreads();
    }

#pragma unroll
    for (int mi = 0; mi < 2; mi++) {
        int r0 = m0 + wm + mi * 16 + gid;
#pragma unroll
        for (int ni = 0; ni < NI; ni++) {
            int c = wn + ni * 8 + 2 * tig;
            float b0 = bias[c], b1 = bias[c + 1];
            if (r0 < N_NODES) {
                float2 o = make_float2(fmaxf(acc[mi][ni][0] + b0, 0.f),
                                       fmaxf(acc[mi][ni][1] + b1, 0.f));
                *reinterpret_cast<float2*>(&X[(size_t)r0 * 128 + c]) = o;
            }
            if (r0 + 8 < N_NODES) {
                float2 o = make_float2(fmaxf(acc[mi][ni][2] + b0, 0.f),
                                       fmaxf(acc[mi][ni][3] + b1, 0.f));
                *reinterpret_cast<float2*>(&X[(size_t)(r0 + 8) * 128 + c]) = o;
            }
        }
    }
}

// ---------------- GEMM1: [xp | agg_init] = [relu(A@wp+bp) | A@wr+bl] --------
// BM=64, BN=IND+64, 8 warps (2M x 4N), NI=BN/32.
template<int IND, bool HAS_RN>
__global__ __launch_bounds__(256, 2) void gemm1_kernel(
    const float* __restrict__ Xin, const float* __restrict__ rn,
    const float* __restrict__ wp, const float* __restrict__ bp,
    const float* __restrict__ wr, const float* __restrict__ bl,
    float* __restrict__ xp, float* __restrict__ agg)
{
    constexpr int BN = IND + 64, NI = BN / 32;
    __shared__ uint32_t Ah[16 * 64];
    __shared__ uint32_t Al[16 * 64];
    __shared__ uint32_t Bh[16 * BN];
    __shared__ uint32_t Bl[16 * BN];
    const int tid = threadIdx.x, lane = tid & 31, wid = tid >> 5;
    const int gid = lane >> 2, tig = lane & 3;
    const int wm = (wid & 1) * 32, wn = (wid >> 1) * (BN / 4);
    const int m0 = blockIdx.x * 64;
    float acc[2][NI][4] = {};

    for (int k0 = 0; k0 < IND; k0 += 16) {
#pragma unroll
        for (int i = 0; i < 4; i++) {
            int idx = tid + i * 256; int m = idx >> 4, k = idx & 15;
            int mg = m0 + m, kg = k0 + k;
            float v = 0.f;
            if (mg < N_NODES) {
                v = Xin[(size_t)mg * IND + kg];
                if (HAS_RN) v *= rn[mg];
            }
            uint32_t h, l; split_tf32(v, h, l);
            Ah[idxA(k, m)] = h; Al[idxA(k, m)] = l;
        }
#pragma unroll
        for (int i = 0; i < BN / 16; i++) {
            int idx = tid + i * 256; int k = idx / BN, n = idx % BN;
            int kg = k0 + k;
            float v = (n < IND) ? wp[kg * IND + n] : wr[kg * 64 + (n - IND)];
            uint32_t h, l; split_tf32(v, h, l);
            Bh[idxB<BN>(k, n)] = h; Bl[idxB<BN>(k, n)] = l;
        }
        __syncthreads();
        mma_ktile<BN, NI>(Ah, Al, Bh, Bl, wm, wn, gid, tig, acc);
        __syncthreads();
    }

#pragma unroll
    for (int mi = 0; mi < 2; mi++) {
        int r0 = m0 + wm + mi * 16 + gid;
#pragma unroll
        for (int ni = 0; ni < NI; ni++) {
            int c = wn + ni * 8 + 2 * tig;
            float b0, b1;
            if (c < IND) { b0 = bp[c]; b1 = bp[c + 1]; }
            else         { b0 = bl[c - IND]; b1 = bl[c - IND + 1]; }
#pragma unroll
            for (int h = 0; h < 2; h++) {
                int r = r0 + h * 8;
                if (r >= N_NODES) continue;
                float v0 = acc[mi][ni][2 * h]     + b0;
                float v1 = acc[mi][ni][2 * h + 1] + b1;
                if (c < IND) {
                    float2 o = make_float2(fmaxf(v0, 0.f), fmaxf(v1, 0.f));
                    *reinterpret_cast<float2*>(&xp[(size_t)r * IND + c]) = o;
                } else {
                    float2 o = make_float2(v0, v1);
                    *reinterpret_cast<float2*>(&agg[(size_t)r * 64 + (c - IND)]) = o;
                }
            }
        }
    }
}

// ---------------- GEMM2: y = xp @ wl, (N,64) ----------------
// BM=64, BN=64, 8 warps (2M x 4N), NI=2.
template<int IND>
__global__ __launch_bounds__(256, 2) void gemm2_kernel(
    const float* __restrict__ xp, const float* __restrict__ wl, float* __restrict__ y)
{
    constexpr int BN = 64, NI = 2;
    __shared__ uint32_t Ah[16 * 64];
    __shared__ uint32_t Al[16 * 64];
    __shared__ uint32_t Bh[16 * BN];
    __shared__ uint32_t Bl[16 * BN];
    const int tid = threadIdx.x, lane = tid & 31, wid = tid >> 5;
    const int gid = lane >> 2, tig = lane & 3;
    const int wm = (wid & 1) * 32, wn = (wid >> 1) * 16;
    const int m0 = blockIdx.x * 64;
    float acc[2][NI][4] = {};

    for (int k0 = 0; k0 < IND; k0 += 16) {
#pragma unroll
        for (int i = 0; i < 4; i++) {
            int idx = tid + i * 256; int m = idx >> 4, k = idx & 15;
            int mg = m0 + m, kg = k0 + k;
            float v = (mg < N_NODES) ? xp[(size_t)mg * IND + kg] : 0.f;
            uint32_t h, l; split_tf32(v, h, l);
            Ah[idxA(k, m)] = h; Al[idxA(k, m)] = l;
        }
#pragma unroll
        for (int i = 0; i < 4; i++) {
            int idx = tid + i * 256; int k = idx >> 6, n = idx & 63;
            uint32_t h, l; split_tf32(wl[(k0 + k) * 64 + n], h, l);
            Bh[idxB<BN>(k, n)] = h; Bl[idxB<BN>(k, n)] = l;
        }
        __syncthreads();
        mma_ktile<BN, NI>(Ah, Al, Bh, Bl, wm, wn, gid, tig, acc);
        __syncthreads();
    }
#pragma unroll
    for (int mi = 0; mi < 2; mi++) {
        int r0 = m0 + wm + mi * 16 + gid;
#pragma unroll
        for (int ni = 0; ni < NI; ni++) {
            int c = wn + ni * 8 + 2 * tig;
            if (r0 < N_NODES) {
                float2 o = make_float2(acc[mi][ni][0], acc[mi][ni][1]);
                *reinterpret_cast<float2*>(&y[(size_t)r0 * 64 + c]) = o;
            }
            if (r0 + 8 < N_NODES) {
                float2 o = make_float2(acc[mi][ni][2], acc[mi][ni][3]);
                *reinterpret_cast<float2*>(&y[(size_t)(r0 + 8) * 64 + c]) = o;
            }
        }
    }
}

// ---------------- scatter: agg[dst] += y[src] * deg_inv[dst], 64-wide -------
__global__ void scatter_kernel(const float* __restrict__ y, const int* __restrict__ src,
                               const int* __restrict__ dst, float* __restrict__ agg) {
    size_t t = (size_t)blockIdx.x * blockDim.x + threadIdx.x;
    if (t >= (size_t)E_EDGES * 16) return;
    int e = (int)(t >> 4), q = (int)(t & 15);
    int s = src[e], d = dst[e];
    float4 v = reinterpret_cast<const float4*>(y)[(size_t)s * 16 + q];
    float di = g_deg[d];
    float* p = agg + (size_t)d * 64 + q * 4;
    asm volatile("red.global.add.v4.f32 [%0], {%1,%2,%3,%4};"
                 :: "l"(p), "f"(v.x * di), "f"(v.y * di), "f"(v.z * di), "f"(v.w * di)
                 : "memory");
}

// ---------------- per-row inverse L2 norm ----------------
__global__ void rownorm_kernel(const float* __restrict__ agg) {
    int gw = (blockIdx.x * blockDim.x + threadIdx.x) >> 5;
    int lane = threadIdx.x & 31;
    if (gw >= N_NODES) return;
    float a = agg[(size_t)gw * 64 + lane];
    float b = agg[(size_t)gw * 64 + lane + 32];
    float ss = a * a + b * b;
#pragma unroll
    for (int off = 16; off > 0; off >>= 1) ss += __shfl_xor_sync(0xffffffffu, ss, off);
    if (lane == 0) g_rn[gw] = 1.f / fmaxf(sqrtf(ss), 1e-12f);
}

// ---------------- pooling: direct global atomics ----------
__global__ void pool_kernel(const float* __restrict__ agg, const float* __restrict__ rn,
                            const int* __restrict__ batch) {
    size_t t = (size_t)blockIdx.x * blockDim.x + threadIdx.x;
    if (t >= (size_t)N_NODES * 16) return;
    int n = (int)(t >> 4), q = (int)(t & 15);
    int b = batch[n];
    float4 v = reinterpret_cast<const float4*>(agg)[(size_t)n * 16 + q];
    float r = rn[n];
    v.x *= r; v.y *= r; v.z *= r; v.w *= r;
    int base = b * 64 + q * 4;
    atomicMax(&g_gmax[base + 0], fenc(v.x));
    atomicMax(&g_gmax[base + 1], fenc(v.y));
    atomicMax(&g_gmax[base + 2], fenc(v.z));
    atomicMax(&g_gmax[base + 3], fenc(v.w));
    atomicAdd(&g_gsum[base + 0], v.x);
    atomicAdd(&g_gsum[base + 1], v.y);
    atomicAdd(&g_gsum[base + 2], v.z);
    atomicAdd(&g_gsum[base + 3], v.w);
    if (q == 0) atomicAdd(&g_cnt[b], 1.f);
}

__global__ void final_kernel(const float* __restrict__ pw, const float* __restrict__ pb,
                             float* __restrict__ out) {
    int b = threadIdx.x / 32, lane = threadIdx.x % 32;
    if (b >= NBATCH) return;
    float c = fmaxf(g_cnt[b], 1.f);
    float g0 = fdec(g_gmax[b * 64 + lane])      + g_gsum[b * 64 + lane] / c;
    float g1 = fdec(g_gmax[b * 64 + lane + 32]) + g_gsum[b * 64 + lane + 32] / c;
    float ss = g0 * g0 + g1 * g1;
#pragma unroll
    for (int off = 16; off > 0; off >>= 1) ss += __shfl_xor_sync(0xffffffffu, ss, off);
    float inv = 1.f / sqrtf(ss);
    float o = g0 * inv * pw[lane] + g1 * inv * pw[lane + 32];
#pragma unroll
    for (int off = 16; off > 0; off >>= 1) o += __shfl_xor_sync(0xffffffffu, o, off);
    if (lane == 0) out[b] = o + pb[0];
}

// ---------------- launch ----------------
extern "C" void kernel_launch(void* const* d_in, const int* in_sizes, int n_in,
                              void* d_out, int out_size) {
    const float* node_feat = (const float*)d_in[0];
    const float* cfg       = (const float*)d_in[1];
    const int*   opcode    = (const int*)d_in[2];
    const int*   eidx      = (const int*)d_in[3];
    const int*   batch     = (const int*)d_in[4];
    const float* op_emb    = (const float*)d_in[5];
    const float* type_emb  = (const float*)d_in[6];
    const float* lin_w     = (const float*)d_in[7];
    const float* lin_b     = (const float*)d_in[8];
    const float* post_w    = (const float*)d_in[9];
    const float* post_b    = (const float*)d_in[10];
    const float* wp[3] = {(const float*)d_in[11], (const float*)d_in[16], (const float*)d_in[21]};
    const float* bp[3] = {(const float*)d_in[12], (const float*)d_in[17], (const float*)d_in[22]};
    const float* wl[3] = {(const float*)d_in[13], (const float*)d_in[18], (const float*)d_in[23]};
    const float* bl[3] = {(const float*)d_in[14], (const float*)d_in[19], (const float*)d_in[24]};
    const float* wr[3] = {(const float*)d_in[15], (const float*)d_in[20], (const float*)d_in[25]};
    const int* src = eidx;
    const int* dst = eidx + E_EDGES;

    float *x_, *xp_, *aggA_, *aggB_, *y_, *rn_, *deg_;
    cudaGetSymbolAddress((void**)&x_,    g_x);
    cudaGetSymbolAddress((void**)&xp_,   g_xp);
    cudaGetSymbolAddress((void**)&aggA_, g_aggA);
    cudaGetSymbolAddress((void**)&aggB_, g_aggB);
    cudaGetSymbolAddress((void**)&y_,    g_y);
    cudaGetSymbolAddress((void**)&rn_,   g_rn);
    cudaGetSymbolAddress((void**)&deg_,  g_deg);

    const int T = 256;
    const int GEMM_GRID = (N_NODES + 63) / 64;   // BM=64
    const unsigned SCAT_GRID = (unsigned)(((size_t)E_EDGES * 16 + T - 1) / T);
    const unsigned WARP_GRID = (unsigned)(((size_t)N_NODES * 32 + T - 1) / T);
    const unsigned POOL_GRID = (unsigned)(((size_t)N_NODES * 16 + T - 1) / T);

    // launch order: gemm1<128> stays in the ncu-captured 4th slot
    gemm_initial<<<GEMM_GRID, T>>>(node_feat, cfg, opcode, op_emb, type_emb, lin_w, lin_b, x_); // 1
    zero_f<<<(N_NODES + T - 1) / T, T>>>(deg_, N_NODES);                                        // 2
    deg_kernel<<<(E_EDGES + T - 1) / T, T>>>(dst);                                              // 3
    gemm1_kernel<128, false><<<GEMM_GRID, T>>>(x_, nullptr, wp[0], bp[0], wr[0], bl[0], xp_, aggA_); // 4 (captured)
    deginv_kernel<<<(N_NODES + T - 1) / T, T>>>();                                              // 5
    pool_init_kernel<<<(NBATCH * 64 + T - 1) / T, T>>>();                                       // 6

    // layer 0 (IND=128), continued
    gemm2_kernel<128><<<GEMM_GRID, T>>>(xp_, wl[0], y_);
    scatter_kernel<<<SCAT_GRID, T>>>(y_, src, dst, aggA_);
    rownorm_kernel<<<WARP_GRID, T>>>(aggA_);

    // layer 1 (IND=64)
    gemm1_kernel<64, true><<<GEMM_GRID, T>>>(aggA_, rn_, wp[1], bp[1], wr[1], bl[1], xp_, aggB_);
    gemm2_kernel<64><<<GEMM_GRID, T>>>(xp_, wl[1], y_);
    scatter_kernel<<<SCAT_GRID, T>>>(y_, src, dst, aggB_);
    rownorm_kernel<<<WARP_GRID, T>>>(aggB_);

    // layer 2 (IND=64)
    gemm1_kernel<64, true><<<GEMM_GRID, T>>>(aggB_, rn_, wp[2], bp[2], wr[2], bl[2], xp_, aggA_);
    gemm2_kernel<64><<<GEMM_GRID, T>>>(xp_, wl[2], y_);
    scatter_kernel<<<SCAT_GRID, T>>>(y_, src, dst, aggA_);
    rownorm_kernel<<<WARP_GRID, T>>>(aggA_);

    // pooling on normalized layer-2 output
    pool_kernel<<<POOL_GRID, T>>>(aggA_, rn_, batch);
    final_kernel<<<1, 512>>>(post_w, post_b, (float*)d_out);
}

// round 13
// speedup vs baseline: 2.0818x; 2.0818x over previous
#include <cuda_runtime.h>
#include <math.h>
#include <stdint.h>

#define N_NODES 200000
#define E_EDGES 800000
#define NBATCH  16
#define PK      208   // 193 padded to multiple of 16
#define NBLK    782   // ceil(N_NODES / 256)

// ---------------- scratch (static; no cudaMalloc) ----------------
__device__ __align__(16) float    g_x   [(size_t)N_NODES * 128];
__device__ __align__(16) float    g_xp  [(size_t)N_NODES * 128];
__device__ __align__(16) float    g_aggA[(size_t)N_NODES * 64];
__device__ __align__(16) float    g_aggB[(size_t)N_NODES * 64];
__device__ __align__(16) float    g_y   [(size_t)N_NODES * 64];
__device__ __align__(16) float    g_rn  [N_NODES];
__device__ __align__(16) float    g_deg [N_NODES];
__device__ __align__(16) int      g_degi[N_NODES];
__device__ __align__(16) int      g_bsum[1024];
__device__ __align__(16) int      g_off [N_NODES + 1];
__device__ __align__(16) int      g_cur [N_NODES];
__device__ __align__(16) int      g_elist[E_EDGES];
__device__ __align__(16) unsigned g_gmax[NBATCH * 64];
__device__ __align__(16) float    g_gsum[NBATCH * 64];
__device__ __align__(16) float    g_cnt [NBATCH];

// ---------------- helpers ----------------
__device__ __forceinline__ unsigned fenc(float f) {
    unsigned u = __float_as_uint(f);
    return (u & 0x80000000u) ? ~u : (u | 0x80000000u);
}
__device__ __forceinline__ float fdec(unsigned u) {
    return (u & 0x80000000u) ? __uint_as_float(u & 0x7FFFFFFFu) : __uint_as_float(~u);
}

__global__ void zero_degi() {
    int i = blockIdx.x * blockDim.x + threadIdx.x;
    if (i < N_NODES) g_degi[i] = 0;
}

__global__ void pool_init_kernel() {
    int i = blockIdx.x * blockDim.x + threadIdx.x;
    if (i < NBATCH * 64) { g_gmax[i] = 0u; g_gsum[i] = 0.f; }
    if (i < NBATCH) g_cnt[i] = 0.f;
}

__global__ void deg_kernel(const int* __restrict__ dst) {
    int e = blockIdx.x * blockDim.x + threadIdx.x;
    if (e < E_EDGES) atomicAdd(&g_degi[dst[e]], 1);
}
__global__ void deginv_kernel() {
    int n = blockIdx.x * blockDim.x + threadIdx.x;
    if (n < N_NODES) g_deg[n] = 1.f / (float)max(g_degi[n], 1);
}

// ---------------- CSR build: 3-kernel scan + fill ----------------
__global__ void scan1_kernel() {   // per-block degree sums
    __shared__ int s[256];
    int t = threadIdx.x, i = blockIdx.x * 256 + t;
    s[t] = (i < N_NODES) ? g_degi[i] : 0;
    __syncthreads();
#pragma unroll
    for (int off = 128; off > 0; off >>= 1) {
        if (t < off) s[t] += s[t + off];
        __syncthreads();
    }
    if (t == 0) g_bsum[blockIdx.x] = s[0];
}

__global__ void scan2_kernel() {   // exclusive scan of 782 block sums (1 block, 1024 thr)
    __shared__ int sa[1024], sb[1024];
    int t = threadIdx.x;
    int v = (t < NBLK) ? g_bsum[t] : 0;
    sa[t] = v;
    __syncthreads();
    int* cur = sa; int* nxt = sb;
#pragma unroll
    for (int off = 1; off < 1024; off <<= 1) {
        int x = cur[t];
        if (t >= off) x += cur[t - off];
        nxt[t] = x;
        __syncthreads();
        int* tmp = cur; cur = nxt; nxt = tmp;
    }
    if (t < NBLK) g_bsum[t] = cur[t] - v;   // exclusive
}

__global__ void scan3_kernel() {   // per-element exclusive offsets + cursor init
    __shared__ int sa[256], sb[256];
    int t = threadIdx.x, i = blockIdx.x * 256 + t;
    int v = (i < N_NODES) ? g_degi[i] : 0;
    sa[t] = v;
    __syncthreads();
    int* cur = sa; int* nxt = sb;
#pragma unroll
    for (int off = 1; off < 256; off <<= 1) {
        int x = cur[t];
        if (t >= off) x += cur[t - off];
        nxt[t] = x;
        __syncthreads();
        int* tmp = cur; cur = nxt; nxt = tmp;
    }
    int excl = cur[t] - v + g_bsum[blockIdx.x];
    if (i < N_NODES) { g_off[i] = excl; g_cur[i] = excl; }
    if (i == 0) g_off[N_NODES] = E_EDGES;
}

__global__ void fill_kernel(const int* __restrict__ src, const int* __restrict__ dst) {
    int e = blockIdx.x * blockDim.x + threadIdx.x;
    if (e >= E_EDGES) return;
    int d = dst[e];
    int pos = atomicAdd(&g_cur[d], 1);
    g_elist[pos] = src[e];
}

// ---------------- tf32 split helpers ----------------
__device__ __forceinline__ void split_tf32(float x, uint32_t& h, uint32_t& l) {
    uint32_t hb;
    asm("cvt.rna.tf32.f32 %0, %1;" : "=r"(hb) : "f"(x));
    h = hb;
    l = __float_as_uint(x - __uint_as_float(hb));
}

__device__ __forceinline__ void mma8(float* c, const uint32_t* a, const uint32_t* b) {
    asm("mma.sync.aligned.m16n8k8.row.col.f32.tf32.tf32.f32 "
        "{%0,%1,%2,%3}, {%4,%5,%6,%7}, {%8,%9}, {%0,%1,%2,%3};"
        : "+f"(c[0]), "+f"(c[1]), "+f"(c[2]), "+f"(c[3])
        : "r"(a[0]), "r"(a[1]), "r"(a[2]), "r"(a[3]), "r"(b[0]), "r"(b[1]));
}

// conflict-free swizzled indices (BM=64 A-tile; 4-byte elements)
__device__ __forceinline__ int idxA(int k, int m) { return k * 64 + (m ^ ((k & 3) << 3)); }
template<int BN>
__device__ __forceinline__ int idxB(int k, int n) { return k * BN + (n ^ ((k & 3) << 3)); }

// one BK=16 tile of split-tf32 mma; block tile 64 x BN, 8 warps as 2M x 4N.
template<int BN, int NI>
__device__ __forceinline__ void mma_ktile(const uint32_t* __restrict__ Ah,
                                          const uint32_t* __restrict__ Al,
                                          const uint32_t* __restrict__ Bh,
                                          const uint32_t* __restrict__ Bl,
                                          int wm, int wn, int gid, int tig,
                                          float (&acc)[2][NI][4]) {
#pragma unroll
    for (int kk = 0; kk < 2; kk++) {
        const int kb = kk * 8 + tig;
        uint32_t aH[2][4], aL[2][4];
#pragma unroll
        for (int mi = 0; mi < 2; mi++) {
            int r = wm + mi * 16 + gid;
            aH[mi][0] = Ah[idxA(kb,     r    )];  aL[mi][0] = Al[idxA(kb,     r    )];
            aH[mi][1] = Ah[idxA(kb,     r + 8)];  aL[mi][1] = Al[idxA(kb,     r + 8)];
            aH[mi][2] = Ah[idxA(kb + 4, r    )];  aL[mi][2] = Al[idxA(kb + 4, r    )];
            aH[mi][3] = Ah[idxA(kb + 4, r + 8)];  aL[mi][3] = Al[idxA(kb + 4, r + 8)];
        }
#pragma unroll
        for (int ni = 0; ni < NI; ni++) {
            int n = wn + ni * 8 + gid;
            uint32_t bh[2], bl[2];
            bh[0] = Bh[idxB<BN>(kb, n)];     bh[1] = Bh[idxB<BN>(kb + 4, n)];
            bl[0] = Bl[idxB<BN>(kb, n)];     bl[1] = Bl[idxB<BN>(kb + 4, n)];
#pragma unroll
            for (int mi = 0; mi < 2; mi++) {
                mma8(acc[mi][ni], aH[mi], bh);
                mma8(acc[mi][ni], aH[mi], bl);
                mma8(acc[mi][ni], aL[mi], bh);
            }
        }
    }
}

// ---------------- fused feature gather ----------------
__device__ __forceinline__ float gatherA(const float* __restrict__ nf, const float* __restrict__ cfgf,
                                         const int* __restrict__ opc,
                                         const float* __restrict__ opE, const float* __restrict__ tyE,
                                         int n, int c) {
    if (c < 139) return nf[(size_t)n * 140 + c];
    if (c < 143) { int ty = (int)nf[(size_t)n * 140 + 139]; return tyE[ty * 4 + (c - 139)]; }
    if (c < 175) return opE[opc[n] * 32 + (c - 143)];
    if (c < 193) return cfgf[(size_t)n * 18 + (c - 175)];
    return 0.f;
}

// ---------------- initial GEMM: x = relu(gather(feat) @ W + b), (N,128) ----
__global__ __launch_bounds__(256, 2) void gemm_initial(
    const float* __restrict__ nf, const float* __restrict__ cfgf, const int* __restrict__ opc,
    const float* __restrict__ opE, const float* __restrict__ tyE,
    const float* __restrict__ lin_w,
    const float* __restrict__ bias, float* __restrict__ X)
{
    constexpr int BN = 128, NI = 4;
    __shared__ uint32_t Ah[16 * 64];
    __shared__ uint32_t Al[16 * 64];
    __shared__ uint32_t Bh[16 * BN];
    __shared__ uint32_t Bl[16 * BN];
    const int tid = threadIdx.x, lane = tid & 31, wid = tid >> 5;
    const int gid = lane >> 2, tig = lane & 3;
    const int wm = (wid & 1) * 32, wn = (wid >> 1) * (BN / 4);
    const int m0 = blockIdx.x * 64;
    float acc[2][NI][4] = {};

    for (int k0 = 0; k0 < PK; k0 += 16) {
#pragma unroll
        for (int i = 0; i < 4; i++) {
            int idx = tid + i * 256; int m = idx >> 4, k = idx & 15;
            int mg = m0 + m, kg = k0 + k;
            float v = (mg < N_NODES) ? gatherA(nf, cfgf, opc, opE, tyE, mg, kg) : 0.f;
            uint32_t h, l; split_tf32(v, h, l);
            Ah[idxA(k, m)] = h; Al[idxA(k, m)] = l;
        }
#pragma unroll
        for (int i = 0; i < 8; i++) {
            int idx = tid + i * 256; int k = idx / BN, n = idx % BN;
            int kg = k0 + k;
            float v = (kg < 193) ? lin_w[kg * 128 + n] : 0.f;
            uint32_t h, l; split_tf32(v, h, l);
            Bh[idxB<BN>(k, n)] = h; Bl[idxB<BN>(k, n)] = l;
        }
        __syncthreads();
        mma_ktile<BN, NI>(Ah, Al, Bh, Bl, wm, wn, gid, tig, acc);
        __syncthreads();
    }

#pragma unroll
    for (int mi = 0; mi < 2; mi++) {
        int r0 = m0 + wm + mi * 16 + gid;
#pragma unroll
        for (int ni = 0; ni < NI; ni++) {
            int c = wn + ni * 8 + 2 * tig;
            float b0 = bias[c], b1 = bias[c + 1];
            if (r0 < N_NODES) {
                float2 o = make_float2(fmaxf(acc[mi][ni][0] + b0, 0.f),
                                       fmaxf(acc[mi][ni][1] + b1, 0.f));
                *reinterpret_cast<float2*>(&X[(size_t)r0 * 128 + c]) = o;
            }
            if (r0 + 8 < N_NODES) {
                float2 o = make_float2(fmaxf(acc[mi][ni][2] + b0, 0.f),
                                       fmaxf(acc[mi][ni][3] + b1, 0.f));
                *reinterpret_cast<float2*>(&X[(size_t)(r0 + 8) * 128 + c]) = o;
            }
        }
    }
}

// ---------------- GEMM1: [xp | agg_init] = [relu(A@wp+bp) | A@wr+bl] --------
template<int IND, bool HAS_RN>
__global__ __launch_bounds__(256, 2) void gemm1_kernel(
    const float* __restrict__ Xin, const float* __restrict__ rn,
    const float* __restrict__ wp, const float* __restrict__ bp,
    const float* __restrict__ wr, const float* __restrict__ bl,
    float* __restrict__ xp, float* __restrict__ agg)
{
    constexpr int BN = IND + 64, NI = BN / 32;
    __shared__ uint32_t Ah[16 * 64];
    __shared__ uint32_t Al[16 * 64];
    __shared__ uint32_t Bh[16 * BN];
    __shared__ uint32_t Bl[16 * BN];
    const int tid = threadIdx.x, lane = tid & 31, wid = tid >> 5;
    const int gid = lane >> 2, tig = lane & 3;
    const int wm = (wid & 1) * 32, wn = (wid >> 1) * (BN / 4);
    const int m0 = blockIdx.x * 64;
    float acc[2][NI][4] = {};

    for (int k0 = 0; k0 < IND; k0 += 16) {
#pragma unroll
        for (int i = 0; i < 4; i++) {
            int idx = tid + i * 256; int m = idx >> 4, k = idx & 15;
            int mg = m0 + m, kg = k0 + k;
            float v = 0.f;
            if (mg < N_NODES) {
                v = Xin[(size_t)mg * IND + kg];
                if (HAS_RN) v *= rn[mg];
            }
            uint32_t h, l; split_tf32(v, h, l);
            Ah[idxA(k, m)] = h; Al[idxA(k, m)] = l;
        }
#pragma unroll
        for (int i = 0; i < BN / 16; i++) {
            int idx = tid + i * 256; int k = idx / BN, n = idx % BN;
            int kg = k0 + k;
            float v = (n < IND) ? wp[kg * IND + n] : wr[kg * 64 + (n - IND)];
            uint32_t h, l; split_tf32(v, h, l);
            Bh[idxB<BN>(k, n)] = h; Bl[idxB<BN>(k, n)] = l;
        }
        __syncthreads();
        mma_ktile<BN, NI>(Ah, Al, Bh, Bl, wm, wn, gid, tig, acc);
        __syncthreads();
    }

#pragma unroll
    for (int mi = 0; mi < 2; mi++) {
        int r0 = m0 + wm + mi * 16 + gid;
#pragma unroll
        for (int ni = 0; ni < NI; ni++) {
            int c = wn + ni * 8 + 2 * tig;
            float b0, b1;
            if (c < IND) { b0 = bp[c]; b1 = bp[c + 1]; }
            else         { b0 = bl[c - IND]; b1 = bl[c - IND + 1]; }
#pragma unroll
            for (int h = 0; h < 2; h++) {
                int r = r0 + h * 8;
                if (r >= N_NODES) continue;
                float v0 = acc[mi][ni][2 * h]     + b0;
                float v1 = acc[mi][ni][2 * h + 1] + b1;
                if (c < IND) {
                    float2 o = make_float2(fmaxf(v0, 0.f), fmaxf(v1, 0.f));
                    *reinterpret_cast<float2*>(&xp[(size_t)r * IND + c]) = o;
                } else {
                    float2 o = make_float2(v0, v1);
                    *reinterpret_cast<float2*>(&agg[(size_t)r * 64 + (c - IND)]) = o;
                }
            }
        }
    }
}

// ---------------- GEMM2: y = xp @ wl, (N,64) ----------------
template<int IND>
__global__ __launch_bounds__(256, 2) void gemm2_kernel(
    const float* __restrict__ xp, const float* __restrict__ wl, float* __restrict__ y)
{
    constexpr int BN = 64, NI = 2;
    __shared__ uint32_t Ah[16 * 64];
    __shared__ uint32_t Al[16 * 64];
    __shared__ uint32_t Bh[16 * BN];
    __shared__ uint32_t Bl[16 * BN];
    const int tid = threadIdx.x, lane = tid & 31, wid = tid >> 5;
    const int gid = lane >> 2, tig = lane & 3;
    const int wm = (wid & 1) * 32, wn = (wid >> 1) * 16;
    const int m0 = blockIdx.x * 64;
    float acc[2][NI][4] = {};

    for (int k0 = 0; k0 < IND; k0 += 16) {
#pragma unroll
        for (int i = 0; i < 4; i++) {
            int idx = tid + i * 256; int m = idx >> 4, k = idx & 15;
            int mg = m0 + m, kg = k0 + k;
            float v = (mg < N_NODES) ? xp[(size_t)mg * IND + kg] : 0.f;
            uint32_t h, l; split_tf32(v, h, l);
            Ah[idxA(k, m)] = h; Al[idxA(k, m)] = l;
        }
#pragma unroll
        for (int i = 0; i < 4; i++) {
            int idx = tid + i * 256; int k = idx >> 6, n = idx & 63;
            uint32_t h, l; split_tf32(wl[(k0 + k) * 64 + n], h, l);
            Bh[idxB<BN>(k, n)] = h; Bl[idxB<BN>(k, n)] = l;
        }
        __syncthreads();
        mma_ktile<BN, NI>(Ah, Al, Bh, Bl, wm, wn, gid, tig, acc);
        __syncthreads();
    }
#pragma unroll
    for (int mi = 0; mi < 2; mi++) {
        int r0 = m0 + wm + mi * 16 + gid;
#pragma unroll
        for (int ni = 0; ni < NI; ni++) {
            int c = wn + ni * 8 + 2 * tig;
            if (r0 < N_NODES) {
                float2 o = make_float2(acc[mi][ni][0], acc[mi][ni][1]);
                *reinterpret_cast<float2*>(&y[(size_t)r0 * 64 + c]) = o;
            }
            if (r0 + 8 < N_NODES) {
                float2 o = make_float2(acc[mi][ni][2], acc[mi][ni][3]);
                *reinterpret_cast<float2*>(&y[(size_t)(r0 + 8) * 64 + c]) = o;
            }
        }
    }
}

// ---------------- CSR gather + fused rownorm (+ optional pooling) ----------
// one warp per node; lanes stride the 64 dims (2 floats/lane).
template<bool DO_POOL>
__global__ __launch_bounds__(256) void gather_kernel(const float* __restrict__ y,
                                                     float* __restrict__ agg,
                                                     const int* __restrict__ batch) {
    int gw = (blockIdx.x * blockDim.x + threadIdx.x) >> 5;
    int lane = threadIdx.x & 31;
    if (gw >= N_NODES) return;
    int beg = g_off[gw], end = g_off[gw + 1];
    float s0 = 0.f, s1 = 0.f;
    int i = beg;
    for (; i + 2 <= end; i += 2) {          // unroll-2 for MLP
        int sA = g_elist[i], sB = g_elist[i + 1];
        const float* pA = y + (size_t)sA * 64;
        const float* pB = y + (size_t)sB * 64;
        float a0 = pA[lane], a1 = pA[lane + 32];
        float b0 = pB[lane], b1 = pB[lane + 32];
        s0 += a0 + b0; s1 += a1 + b1;
    }
    if (i < end) {
        const float* pA = y + (size_t)g_elist[i] * 64;
        s0 += pA[lane]; s1 += pA[lane + 32];
    }
    float di = g_deg[gw];
    float a0 = agg[(size_t)gw * 64 + lane]      + di * s0;
    float a1 = agg[(size_t)gw * 64 + lane + 32] + di * s1;
    agg[(size_t)gw * 64 + lane]      = a0;
    agg[(size_t)gw * 64 + lane + 32] = a1;

    float ss = a0 * a0 + a1 * a1;
#pragma unroll
    for (int off = 16; off > 0; off >>= 1) ss += __shfl_xor_sync(0xffffffffu, ss, off);
    float rn = 1.f / fmaxf(sqrtf(ss), 1e-12f);
    if (lane == 0) g_rn[gw] = rn;

    if (DO_POOL) {
        float v0 = a0 * rn, v1 = a1 * rn;
        int b = batch[gw];
        atomicMax(&g_gmax[b * 64 + lane],      fenc(v0));
        atomicMax(&g_gmax[b * 64 + lane + 32], fenc(v1));
        atomicAdd(&g_gsum[b * 64 + lane],      v0);
        atomicAdd(&g_gsum[b * 64 + lane + 32], v1);
        if (lane == 0) atomicAdd(&g_cnt[b], 1.f);
    }
}

__global__ void final_kernel(const float* __restrict__ pw, const float* __restrict__ pb,
                             float* __restrict__ out) {
    int b = threadIdx.x / 32, lane = threadIdx.x % 32;
    if (b >= NBATCH) return;
    float c = fmaxf(g_cnt[b], 1.f);
    float g0 = fdec(g_gmax[b * 64 + lane])      + g_gsum[b * 64 + lane] / c;
    float g1 = fdec(g_gmax[b * 64 + lane + 32]) + g_gsum[b * 64 + lane + 32] / c;
    float ss = g0 * g0 + g1 * g1;
#pragma unroll
    for (int off = 16; off > 0; off >>= 1) ss += __shfl_xor_sync(0xffffffffu, ss, off);
    float inv = 1.f / sqrtf(ss);
    float o = g0 * inv * pw[lane] + g1 * inv * pw[lane + 32];
#pragma unroll
    for (int off = 16; off > 0; off >>= 1) o += __shfl_xor_sync(0xffffffffu, o, off);
    if (lane == 0) out[b] = o + pb[0];
}

// ---------------- launch ----------------
extern "C" void kernel_launch(void* const* d_in, const int* in_sizes, int n_in,
                              void* d_out, int out_size) {
    const float* node_feat = (const float*)d_in[0];
    const float* cfg       = (const float*)d_in[1];
    const int*   opcode    = (const int*)d_in[2];
    const int*   eidx      = (const int*)d_in[3];
    const int*   batch     = (const int*)d_in[4];
    const float* op_emb    = (const float*)d_in[5];
    const float* type_emb  = (const float*)d_in[6];
    const float* lin_w     = (const float*)d_in[7];
    const float* lin_b     = (const float*)d_in[8];
    const float* post_w    = (const float*)d_in[9];
    const float* post_b    = (const float*)d_in[10];
    const float* wp[3] = {(const float*)d_in[11], (const float*)d_in[16], (const float*)d_in[21]};
    const float* bp[3] = {(const float*)d_in[12], (const float*)d_in[17], (const float*)d_in[22]};
    const float* wl[3] = {(const float*)d_in[13], (const float*)d_in[18], (const float*)d_in[23]};
    const float* bl[3] = {(const float*)d_in[14], (const float*)d_in[19], (const float*)d_in[24]};
    const float* wr[3] = {(const float*)d_in[15], (const float*)d_in[20], (const float*)d_in[25]};
    const int* src = eidx;
    const int* dst = eidx + E_EDGES;

    float *x_, *xp_, *aggA_, *aggB_, *y_, *rn_;
    cudaGetSymbolAddress((void**)&x_,    g_x);
    cudaGetSymbolAddress((void**)&xp_,   g_xp);
    cudaGetSymbolAddress((void**)&aggA_, g_aggA);
    cudaGetSymbolAddress((void**)&aggB_, g_aggB);
    cudaGetSymbolAddress((void**)&y_,    g_y);
    cudaGetSymbolAddress((void**)&rn_,   g_rn);

    const int T = 256;
    const int GEMM_GRID = (N_NODES + 63) / 64;   // BM=64
    const unsigned GATH_GRID = (unsigned)(((size_t)N_NODES * 32 + T - 1) / T);

    // CSR build + init
    gemm_initial<<<GEMM_GRID, T>>>(node_feat, cfg, opcode, op_emb, type_emb, lin_w, lin_b, x_);
    zero_degi<<<NBLK, T>>>();
    deg_kernel<<<(E_EDGES + T - 1) / T, T>>>(dst);
    scan1_kernel<<<NBLK, T>>>();
    scan2_kernel<<<1, 1024>>>();
    scan3_kernel<<<NBLK, T>>>();
    fill_kernel<<<(E_EDGES + T - 1) / T, T>>>(src, dst);
    deginv_kernel<<<(N_NODES + T - 1) / T, T>>>();
    pool_init_kernel<<<(NBATCH * 64 + T - 1) / T, T>>>();

    // layer 0 (IND=128)
    gemm1_kernel<128, false><<<GEMM_GRID, T>>>(x_, nullptr, wp[0], bp[0], wr[0], bl[0], xp_, aggA_);
    gemm2_kernel<128><<<GEMM_GRID, T>>>(xp_, wl[0], y_);
    gather_kernel<false><<<GATH_GRID, T>>>(y_, aggA_, batch);

    // layer 1 (IND=64)
    gemm1_kernel<64, true><<<GEMM_GRID, T>>>(aggA_, rn_, wp[1], bp[1], wr[1], bl[1], xp_, aggB_);
    gemm2_kernel<64><<<GEMM_GRID, T>>>(xp_, wl[1], y_);
    gather_kernel<false><<<GATH_GRID, T>>>(y_, aggB_, batch);

    // layer 2 (IND=64), pooling fused into gather
    gemm1_kernel<64, true><<<GEMM_GRID, T>>>(aggB_, rn_, wp[2], bp[2], wr[2], bl[2], xp_, aggA_);
    gemm2_kernel<64><<<GEMM_GRID, T>>>(xp_, wl[2], y_);
    gather_kernel<true><<<GATH_GRID, T>>>(y_, aggA_, batch);

    final_kernel<<<1, 512>>>(post_w, post_b, (float*)d_out);
}

// round 14
// speedup vs baseline: 2.1109x; 1.0140x over previous
#include <cuda_runtime.h>
#include <math.h>
#include <stdint.h>

#define N_NODES 200000
#define E_EDGES 800000
#define NBATCH  16
#define PK      208   // 193 padded to multiple of 16
#define NBLK    782   // ceil(N_NODES / 256)

// ---------------- scratch (static; no cudaMalloc) ----------------
__device__ __align__(16) float    g_x   [(size_t)N_NODES * 128];
__device__ __align__(16) float    g_aggA[(size_t)N_NODES * 64];
__device__ __align__(16) float    g_aggB[(size_t)N_NODES * 64];
__device__ __align__(16) float    g_y   [(size_t)N_NODES * 64];
__device__ __align__(16) float    g_rn  [N_NODES];
__device__ __align__(16) float    g_deg [N_NODES];
__device__ __align__(16) int      g_degi[N_NODES];
__device__ __align__(16) int      g_bsum[1024];
__device__ __align__(16) int      g_off [N_NODES + 1];
__device__ __align__(16) int      g_cur [N_NODES];
__device__ __align__(16) int      g_elist[E_EDGES];
__device__ __align__(16) unsigned g_gmax[NBATCH * 64];
__device__ __align__(16) float    g_gsum[NBATCH * 64];
__device__ __align__(16) float    g_cnt [NBATCH];

// ---------------- helpers ----------------
__device__ __forceinline__ unsigned fenc(float f) {
    unsigned u = __float_as_uint(f);
    return (u & 0x80000000u) ? ~u : (u | 0x80000000u);
}
__device__ __forceinline__ float fdec(unsigned u) {
    return (u & 0x80000000u) ? __uint_as_float(u & 0x7FFFFFFFu) : __uint_as_float(~u);
}

__global__ void zero_degi() {
    int i = blockIdx.x * blockDim.x + threadIdx.x;
    if (i < N_NODES) g_degi[i] = 0;
}

__global__ void pool_init_kernel() {
    int i = blockIdx.x * blockDim.x + threadIdx.x;
    if (i < NBATCH * 64) { g_gmax[i] = 0u; g_gsum[i] = 0.f; }
    if (i < NBATCH) g_cnt[i] = 0.f;
}

__global__ void deg_kernel(const int* __restrict__ dst) {
    int e = blockIdx.x * blockDim.x + threadIdx.x;
    if (e < E_EDGES) atomicAdd(&g_degi[dst[e]], 1);
}
__global__ void deginv_kernel() {
    int n = blockIdx.x * blockDim.x + threadIdx.x;
    if (n < N_NODES) g_deg[n] = 1.f / (float)max(g_degi[n], 1);
}

// ---------------- CSR build: 3-kernel scan + fill ----------------
__global__ void scan1_kernel() {
    __shared__ int s[256];
    int t = threadIdx.x, i = blockIdx.x * 256 + t;
    s[t] = (i < N_NODES) ? g_degi[i] : 0;
    __syncthreads();
#pragma unroll
    for (int off = 128; off > 0; off >>= 1) {
        if (t < off) s[t] += s[t + off];
        __syncthreads();
    }
    if (t == 0) g_bsum[blockIdx.x] = s[0];
}

__global__ void scan2_kernel() {
    __shared__ int sa[1024], sb[1024];
    int t = threadIdx.x;
    int v = (t < NBLK) ? g_bsum[t] : 0;
    sa[t] = v;
    __syncthreads();
    int* cur = sa; int* nxt = sb;
#pragma unroll
    for (int off = 1; off < 1024; off <<= 1) {
        int x = cur[t];
        if (t >= off) x += cur[t - off];
        nxt[t] = x;
        __syncthreads();
        int* tmp = cur; cur = nxt; nxt = tmp;
    }
    if (t < NBLK) g_bsum[t] = cur[t] - v;
}

__global__ void scan3_kernel() {
    __shared__ int sa[256], sb[256];
    int t = threadIdx.x, i = blockIdx.x * 256 + t;
    int v = (i < N_NODES) ? g_degi[i] : 0;
    sa[t] = v;
    __syncthreads();
    int* cur = sa; int* nxt = sb;
#pragma unroll
    for (int off = 1; off < 256; off <<= 1) {
        int x = cur[t];
        if (t >= off) x += cur[t - off];
        nxt[t] = x;
        __syncthreads();
        int* tmp = cur; cur = nxt; nxt = tmp;
    }
    int excl = cur[t] - v + g_bsum[blockIdx.x];
    if (i < N_NODES) { g_off[i] = excl; g_cur[i] = excl; }
    if (i == 0) g_off[N_NODES] = E_EDGES;
}

__global__ void fill_kernel(const int* __restrict__ src, const int* __restrict__ dst) {
    int e = blockIdx.x * blockDim.x + threadIdx.x;
    if (e >= E_EDGES) return;
    int d = dst[e];
    int pos = atomicAdd(&g_cur[d], 1);
    g_elist[pos] = src[e];
}

// ---------------- tf32 split helpers ----------------
__device__ __forceinline__ void split_tf32(float x, uint32_t& h, uint32_t& l) {
    uint32_t hb;
    asm("cvt.rna.tf32.f32 %0, %1;" : "=r"(hb) : "f"(x));
    h = hb;
    l = __float_as_uint(x - __uint_as_float(hb));
}

__device__ __forceinline__ void mma8(float* c, const uint32_t* a, const uint32_t* b) {
    asm("mma.sync.aligned.m16n8k8.row.col.f32.tf32.tf32.f32 "
        "{%0,%1,%2,%3}, {%4,%5,%6,%7}, {%8,%9}, {%0,%1,%2,%3};"
        : "+f"(c[0]), "+f"(c[1]), "+f"(c[2]), "+f"(c[3])
        : "r"(a[0]), "r"(a[1]), "r"(a[2]), "r"(a[3]), "r"(b[0]), "r"(b[1]));
}

// conflict-free swizzled indices (BM=64 A-tile; 4-byte elements)
__device__ __forceinline__ int idxA(int k, int m) { return k * 64 + (m ^ ((k & 3) << 3)); }
template<int BN>
__device__ __forceinline__ int idxB(int k, int n) { return k * BN + (n ^ ((k & 3) << 3)); }

// one BK=16 tile of split-tf32 mma; block tile 64 x BN, 8 warps as 2M x 4N.
template<int BN, int NI>
__device__ __forceinline__ void mma_ktile(const uint32_t* __restrict__ Ah,
                                          const uint32_t* __restrict__ Al,
                                          const uint32_t* __restrict__ Bh,
                                          const uint32_t* __restrict__ Bl,
                                          int wm, int wn, int gid, int tig,
                                          float (&acc)[2][NI][4]) {
#pragma unroll
    for (int kk = 0; kk < 2; kk++) {
        const int kb = kk * 8 + tig;
        uint32_t aH[2][4], aL[2][4];
#pragma unroll
        for (int mi = 0; mi < 2; mi++) {
            int r = wm + mi * 16 + gid;
            aH[mi][0] = Ah[idxA(kb,     r    )];  aL[mi][0] = Al[idxA(kb,     r    )];
            aH[mi][1] = Ah[idxA(kb,     r + 8)];  aL[mi][1] = Al[idxA(kb,     r + 8)];
            aH[mi][2] = Ah[idxA(kb + 4, r    )];  aL[mi][2] = Al[idxA(kb + 4, r    )];
            aH[mi][3] = Ah[idxA(kb + 4, r + 8)];  aL[mi][3] = Al[idxA(kb + 4, r + 8)];
        }
#pragma unroll
        for (int ni = 0; ni < NI; ni++) {
            int n = wn + ni * 8 + gid;
            uint32_t bh[2], bl[2];
            bh[0] = Bh[idxB<BN>(kb, n)];     bh[1] = Bh[idxB<BN>(kb + 4, n)];
            bl[0] = Bl[idxB<BN>(kb, n)];     bl[1] = Bl[idxB<BN>(kb + 4, n)];
#pragma unroll
            for (int mi = 0; mi < 2; mi++) {
                mma8(acc[mi][ni], aH[mi], bh);
                mma8(acc[mi][ni], aH[mi], bl);
                mma8(acc[mi][ni], aL[mi], bh);
            }
        }
    }
}

// ---------------- fused feature gather ----------------
__device__ __forceinline__ float gatherA(const float* __restrict__ nf, const float* __restrict__ cfgf,
                                         const int* __restrict__ opc,
                                         const float* __restrict__ opE, const float* __restrict__ tyE,
                                         int n, int c) {
    if (c < 139) return nf[(size_t)n * 140 + c];
    if (c < 143) { int ty = (int)nf[(size_t)n * 140 + 139]; return tyE[ty * 4 + (c - 139)]; }
    if (c < 175) return opE[opc[n] * 32 + (c - 143)];
    if (c < 193) return cfgf[(size_t)n * 18 + (c - 175)];
    return 0.f;
}

// ---------------- initial GEMM: x = relu(gather(feat) @ W + b), (N,128) ----
__global__ __launch_bounds__(256, 2) void gemm_initial(
    const float* __restrict__ nf, const float* __restrict__ cfgf, const int* __restrict__ opc,
    const float* __restrict__ opE, const float* __restrict__ tyE,
    const float* __restrict__ lin_w,
    const float* __restrict__ bias, float* __restrict__ X)
{
    constexpr int BN = 128, NI = 4;
    __shared__ uint32_t Ah[16 * 64];
    __shared__ uint32_t Al[16 * 64];
    __shared__ uint32_t Bh[16 * BN];
    __shared__ uint32_t Bl[16 * BN];
    const int tid = threadIdx.x, lane = tid & 31, wid = tid >> 5;
    const int gid = lane >> 2, tig = lane & 3;
    const int wm = (wid & 1) * 32, wn = (wid >> 1) * (BN / 4);
    const int m0 = blockIdx.x * 64;
    float acc[2][NI][4] = {};

    for (int k0 = 0; k0 < PK; k0 += 16) {
#pragma unroll
        for (int i = 0; i < 4; i++) {
            int idx = tid + i * 256; int m = idx >> 4, k = idx & 15;
            int mg = m0 + m, kg = k0 + k;
            float v = (mg < N_NODES) ? gatherA(nf, cfgf, opc, opE, tyE, mg, kg) : 0.f;
            uint32_t h, l; split_tf32(v, h, l);
            Ah[idxA(k, m)] = h; Al[idxA(k, m)] = l;
        }
#pragma unroll
        for (int i = 0; i < 8; i++) {
            int idx = tid + i * 256; int k = idx / BN, n = idx % BN;
            int kg = k0 + k;
            float v = (kg < 193) ? lin_w[kg * 128 + n] : 0.f;
            uint32_t h, l; split_tf32(v, h, l);
            Bh[idxB<BN>(k, n)] = h; Bl[idxB<BN>(k, n)] = l;
        }
        __syncthreads();
        mma_ktile<BN, NI>(Ah, Al, Bh, Bl, wm, wn, gid, tig, acc);
        __syncthreads();
    }

#pragma unroll
    for (int mi = 0; mi < 2; mi++) {
        int r0 = m0 + wm + mi * 16 + gid;
#pragma unroll
        for (int ni = 0; ni < NI; ni++) {
            int c = wn + ni * 8 + 2 * tig;
            float b0 = bias[c], b1 = bias[c + 1];
            if (r0 < N_NODES) {
                float2 o = make_float2(fmaxf(acc[mi][ni][0] + b0, 0.f),
                                       fmaxf(acc[mi][ni][1] + b1, 0.f));
                *reinterpret_cast<float2*>(&X[(size_t)r0 * 128 + c]) = o;
            }
            if (r0 + 8 < N_NODES) {
                float2 o = make_float2(fmaxf(acc[mi][ni][2] + b0, 0.f),
                                       fmaxf(acc[mi][ni][3] + b1, 0.f));
                *reinterpret_cast<float2*>(&X[(size_t)(r0 + 8) * 128 + c]) = o;
            }
        }
    }
}

// ---------------- fused layer: phase1 [P | agg_init], phase2 y = P @ wl -----
// BM=64; P kept pre-split in dynamic SMEM; 2 CTAs/SM.
template<int IND, bool HAS_RN>
__global__ __launch_bounds__(256, 2) void fused_layer(
    const float* __restrict__ Xin, const float* __restrict__ rn,
    const float* __restrict__ wp, const float* __restrict__ bp,
    const float* __restrict__ wr, const float* __restrict__ bl,
    const float* __restrict__ wl,
    float* __restrict__ agg, float* __restrict__ y)
{
    constexpr int BN1 = IND + 64, NI1 = BN1 / 32;
    extern __shared__ uint32_t sh[];
    uint32_t* Ah = sh;                       // 16*64
    uint32_t* Al = Ah + 16 * 64;             // 16*64
    uint32_t* Bh = Al + 16 * 64;             // 16*BN1
    uint32_t* Bl = Bh + 16 * BN1;            // 16*BN1
    uint32_t* Ph = Bl + 16 * BN1;            // IND*64
    uint32_t* Pl = Ph + IND * 64;            // IND*64
    const int tid = threadIdx.x, lane = tid & 31, wid = tid >> 5;
    const int gid = lane >> 2, tig = lane & 3;
    const int wm = (wid & 1) * 32;
    const int wn1 = (wid >> 1) * (BN1 / 4);
    const int m0 = blockIdx.x * 64;

    // ---- phase 1: [P | agg_init] = [relu(A@wp+bp) | A@wr+bl] ----
    {
        float acc[2][NI1][4] = {};
        for (int k0 = 0; k0 < IND; k0 += 16) {
#pragma unroll
            for (int i = 0; i < 4; i++) {
                int idx = tid + i * 256; int m = idx >> 4, k = idx & 15;
                int mg = m0 + m, kg = k0 + k;
                float v = 0.f;
                if (mg < N_NODES) {
                    v = Xin[(size_t)mg * IND + kg];
                    if (HAS_RN) v *= rn[mg];
                }
                uint32_t h, l; split_tf32(v, h, l);
                Ah[idxA(k, m)] = h; Al[idxA(k, m)] = l;
            }
#pragma unroll
            for (int i = 0; i < BN1 / 16; i++) {
                int idx = tid + i * 256; int k = idx / BN1, n = idx % BN1;
                int kg = k0 + k;
                float v = (n < IND) ? wp[kg * IND + n] : wr[kg * 64 + (n - IND)];
                uint32_t h, l; split_tf32(v, h, l);
                Bh[idxB<BN1>(k, n)] = h; Bl[idxB<BN1>(k, n)] = l;
            }
            __syncthreads();
            mma_ktile<BN1, NI1>(Ah, Al, Bh, Bl, wm, wn1, gid, tig, acc);
            __syncthreads();
        }

        // epilogue: P (pre-split) -> SMEM, agg-init -> global
#pragma unroll
        for (int mi = 0; mi < 2; mi++) {
            int lr0 = wm + mi * 16 + gid;
#pragma unroll
            for (int ni = 0; ni < NI1; ni++) {
                int c = wn1 + ni * 8 + 2 * tig;
                float b0, b1;
                if (c < IND) { b0 = bp[c]; b1 = bp[c + 1]; }
                else         { b0 = bl[c - IND]; b1 = bl[c - IND + 1]; }
#pragma unroll
                for (int h = 0; h < 2; h++) {
                    int lr = lr0 + h * 8;
                    float v0 = acc[mi][ni][2 * h]     + b0;
                    float v1 = acc[mi][ni][2 * h + 1] + b1;
                    if (c < IND) {
                        uint32_t h0, l0, h1, l1;
                        split_tf32(fmaxf(v0, 0.f), h0, l0);
                        split_tf32(fmaxf(v1, 0.f), h1, l1);
                        Ph[idxA(c,     lr)] = h0; Pl[idxA(c,     lr)] = l0;
                        Ph[idxA(c + 1, lr)] = h1; Pl[idxA(c + 1, lr)] = l1;
                    } else {
                        int r = m0 + lr;
                        if (r < N_NODES) {
                            float2 o = make_float2(v0, v1);
                            *reinterpret_cast<float2*>(&agg[(size_t)r * 64 + (c - IND)]) = o;
                        }
                    }
                }
            }
        }
    }
    __syncthreads();

    // ---- phase 2: y = P @ wl (BN=64, NI=2) ----
    {
        constexpr int NI2 = 2;
        const int wn2 = (wid >> 1) * 16;
        float acc[2][NI2][4] = {};
        for (int k0 = 0; k0 < IND; k0 += 16) {
#pragma unroll
            for (int i = 0; i < 4; i++) {
                int idx = tid + i * 256; int k = idx >> 6, n = idx & 63;
                uint32_t h, l; split_tf32(wl[(k0 + k) * 64 + n], h, l);
                Bh[idxB<64>(k, n)] = h; Bl[idxB<64>(k, n)] = l;
            }
            __syncthreads();
            mma_ktile<64, NI2>(Ph + k0 * 64, Pl + k0 * 64, Bh, Bl, wm, wn2, gid, tig, acc);
            __syncthreads();
        }
#pragma unroll
        for (int mi = 0; mi < 2; mi++) {
            int r0 = m0 + wm + mi * 16 + gid;
#pragma unroll
            for (int ni = 0; ni < NI2; ni++) {
                int c = wn2 + ni * 8 + 2 * tig;
                if (r0 < N_NODES) {
                    float2 o = make_float2(acc[mi][ni][0], acc[mi][ni][1]);
                    *reinterpret_cast<float2*>(&y[(size_t)r0 * 64 + c]) = o;
                }
                if (r0 + 8 < N_NODES) {
                    float2 o = make_float2(acc[mi][ni][2], acc[mi][ni][3]);
                    *reinterpret_cast<float2*>(&y[(size_t)(r0 + 8) * 64 + c]) = o;
                }
            }
        }
    }
}

// ---------------- CSR gather + fused rownorm (+ optional pooling) ----------
template<bool DO_POOL>
__global__ __launch_bounds__(256) void gather_kernel(const float* __restrict__ y,
                                                     float* __restrict__ agg,
                                                     const int* __restrict__ batch) {
    int gw = (blockIdx.x * blockDim.x + threadIdx.x) >> 5;
    int lane = threadIdx.x & 31;
    if (gw >= N_NODES) return;
    int beg = g_off[gw], end = g_off[gw + 1];
    float s0 = 0.f, s1 = 0.f;
    int i = beg;
    for (; i + 2 <= end; i += 2) {
        int sA = g_elist[i], sB = g_elist[i + 1];
        const float* pA = y + (size_t)sA * 64;
        const float* pB = y + (size_t)sB * 64;
        float a0 = pA[lane], a1 = pA[lane + 32];
        float b0 = pB[lane], b1 = pB[lane + 32];
        s0 += a0 + b0; s1 += a1 + b1;
    }
    if (i < end) {
        const float* pA = y + (size_t)g_elist[i] * 64;
        s0 += pA[lane]; s1 += pA[lane + 32];
    }
    float di = g_deg[gw];
    float a0 = agg[(size_t)gw * 64 + lane]      + di * s0;
    float a1 = agg[(size_t)gw * 64 + lane + 32] + di * s1;
    agg[(size_t)gw * 64 + lane]      = a0;
    agg[(size_t)gw * 64 + lane + 32] = a1;

    float ss = a0 * a0 + a1 * a1;
#pragma unroll
    for (int off = 16; off > 0; off >>= 1) ss += __shfl_xor_sync(0xffffffffu, ss, off);
    float rn = 1.f / fmaxf(sqrtf(ss), 1e-12f);
    if (lane == 0) g_rn[gw] = rn;

    if (DO_POOL) {
        float v0 = a0 * rn, v1 = a1 * rn;
        int b = batch[gw];
        atomicMax(&g_gmax[b * 64 + lane],      fenc(v0));
        atomicMax(&g_gmax[b * 64 + lane + 32], fenc(v1));
        atomicAdd(&g_gsum[b * 64 + lane],      v0);
        atomicAdd(&g_gsum[b * 64 + lane + 32], v1);
        if (lane == 0) atomicAdd(&g_cnt[b], 1.f);
    }
}

__global__ void final_kernel(const float* __restrict__ pw, const float* __restrict__ pb,
                             float* __restrict__ out) {
    int b = threadIdx.x / 32, lane = threadIdx.x % 32;
    if (b >= NBATCH) return;
    float c = fmaxf(g_cnt[b], 1.f);
    float g0 = fdec(g_gmax[b * 64 + lane])      + g_gsum[b * 64 + lane] / c;
    float g1 = fdec(g_gmax[b * 64 + lane + 32]) + g_gsum[b * 64 + lane + 32] / c;
    float ss = g0 * g0 + g1 * g1;
#pragma unroll
    for (int off = 16; off > 0; off >>= 1) ss += __shfl_xor_sync(0xffffffffu, ss, off);
    float inv = 1.f / sqrtf(ss);
    float o = g0 * inv * pw[lane] + g1 * inv * pw[lane + 32];
#pragma unroll
    for (int off = 16; off > 0; off >>= 1) o += __shfl_xor_sync(0xffffffffu, o, off);
    if (lane == 0) out[b] = o + pb[0];
}

// ---------------- launch ----------------
extern "C" void kernel_launch(void* const* d_in, const int* in_sizes, int n_in,
                              void* d_out, int out_size) {
    const float* node_feat = (const float*)d_in[0];
    const float* cfg       = (const float*)d_in[1];
    const int*   opcode    = (const int*)d_in[2];
    const int*   eidx      = (const int*)d_in[3];
    const int*   batch     = (const int*)d_in[4];
    const float* op_emb    = (const float*)d_in[5];
    const float* type_emb  = (const float*)d_in[6];
    const float* lin_w     = (const float*)d_in[7];
    const float* lin_b     = (const float*)d_in[8];
    const float* post_w    = (const float*)d_in[9];
    const float* post_b    = (const float*)d_in[10];
    const float* wp[3] = {(const float*)d_in[11], (const float*)d_in[16], (const float*)d_in[21]};
    const float* bp[3] = {(const float*)d_in[12], (const float*)d_in[17], (const float*)d_in[22]};
    const float* wl[3] = {(const float*)d_in[13], (const float*)d_in[18], (const float*)d_in[23]};
    const float* bl[3] = {(const float*)d_in[14], (const float*)d_in[19], (const float*)d_in[24]};
    const float* wr[3] = {(const float*)d_in[15], (const float*)d_in[20], (const float*)d_in[25]};
    const int* src = eidx;
    const int* dst = eidx + E_EDGES;

    float *x_, *aggA_, *aggB_, *y_, *rn_;
    cudaGetSymbolAddress((void**)&x_,    g_x);
    cudaGetSymbolAddress((void**)&aggA_, g_aggA);
    cudaGetSymbolAddress((void**)&aggB_, g_aggB);
    cudaGetSymbolAddress((void**)&y_,    g_y);
    cudaGetSymbolAddress((void**)&rn_,   g_rn);

    const int T = 256;
    const int GEMM_GRID = (N_NODES + 63) / 64;   // BM=64
    const unsigned GATH_GRID = (unsigned)(((size_t)N_NODES * 32 + T - 1) / T);

    // dynamic smem: (Ah+Al + Bh+Bl + Ph+Pl) * 4B
    const int SM128 = (2 * 16 * 64 + 2 * 16 * 192 + 2 * 128 * 64) * 4;  // 98304
    const int SM64  = (2 * 16 * 64 + 2 * 16 * 128 + 2 * 64 * 64) * 4;   // 57344
    cudaFuncSetAttribute(fused_layer<128, false>, cudaFuncAttributeMaxDynamicSharedMemorySize, SM128);
    cudaFuncSetAttribute(fused_layer<64, true>,   cudaFuncAttributeMaxDynamicSharedMemorySize, SM64);

    // CSR build + init
    gemm_initial<<<GEMM_GRID, T>>>(node_feat, cfg, opcode, op_emb, type_emb, lin_w, lin_b, x_);
    zero_degi<<<NBLK, T>>>();
    deg_kernel<<<(E_EDGES + T - 1) / T, T>>>(dst);
    scan1_kernel<<<NBLK, T>>>();
    scan2_kernel<<<1, 1024>>>();
    scan3_kernel<<<NBLK, T>>>();
    fill_kernel<<<(E_EDGES + T - 1) / T, T>>>(src, dst);
    deginv_kernel<<<(N_NODES + T - 1) / T, T>>>();
    pool_init_kernel<<<(NBATCH * 64 + T - 1) / T, T>>>();

    // layer 0 (IND=128)
    fused_layer<128, false><<<GEMM_GRID, T, SM128>>>(x_, nullptr, wp[0], bp[0], wr[0], bl[0], wl[0], aggA_, y_);
    gather_kernel<false><<<GATH_GRID, T>>>(y_, aggA_, batch);

    // layer 1 (IND=64)
    fused_layer<64, true><<<GEMM_GRID, T, SM64>>>(aggA_, rn_, wp[1], bp[1], wr[1], bl[1], wl[1], aggB_, y_);
    gather_kernel<false><<<GATH_GRID, T>>>(y_, aggB_, batch);

    // layer 2 (IND=64), pooling fused into gather
    fused_layer<64, true><<<GEMM_GRID, T, SM64>>>(aggB_, rn_, wp[2], bp[2], wr[2], bl[2], wl[2], aggA_, y_);
    gather_kernel<true><<<GATH_GRID, T>>>(y_, aggA_, batch);

    final_kernel<<<1, 512>>>(post_w, post_b, (float*)d_out);
}